// round 2
// baseline (speedup 1.0000x reference)
#include <cuda_runtime.h>
#include <cuda_bf16.h>
#include <cstdint>
#include <cstddef>

#define HID   1024
#define BATCH 256
#define SEQ   512
#define VOCAB 32000
#define G3    3072   // 3*HID

// ---------------- persistent scratch (__device__ globals; no allocs) ----------------
__device__ __nv_bfloat16 g_Wih_hi[G3 * HID];
__device__ __nv_bfloat16 g_Wih_lo[G3 * HID];
__device__ __nv_bfloat16 g_Whh_hi[G3 * HID];
__device__ __nv_bfloat16 g_Whh_lo[G3 * HID];
__device__ float         g_E[(size_t)VOCAB * G3];   // emb @ W_ih^T (no bias), 393 MB
__device__ float         g_h0[BATCH * HID];
__device__ float         g_h1[BATCH * HID];

// ---------------- helpers ----------------
__device__ __forceinline__ void split2(float x, __nv_bfloat16 &hi, __nv_bfloat16 &lo) {
    hi = __float2bfloat16_rn(x);
    lo = __float2bfloat16_rn(x - __bfloat162float(hi));
}

__device__ __forceinline__ unsigned pk(__nv_bfloat16 a, __nv_bfloat16 b) {
    // a -> low 16 bits (lower k index), b -> high 16 bits
    return (unsigned)__bfloat16_as_ushort(a) | ((unsigned)__bfloat16_as_ushort(b) << 16);
}

__device__ __forceinline__ void mma16816(float *d, const unsigned *a, const unsigned *b) {
    asm volatile(
        "mma.sync.aligned.m16n8k16.row.col.f32.bf16.bf16.f32 "
        "{%0,%1,%2,%3},{%4,%5,%6,%7},{%8,%9},{%0,%1,%2,%3};\n"
        : "+f"(d[0]), "+f"(d[1]), "+f"(d[2]), "+f"(d[3])
        : "r"(a[0]), "r"(a[1]), "r"(a[2]), "r"(a[3]), "r"(b[0]), "r"(b[1]));
}

// ---------------- kernel: split weights into bf16 hi/lo ----------------
__global__ void k_split(const float *__restrict__ Wih, const float *__restrict__ Whh) {
    int i = blockIdx.x * blockDim.x + threadIdx.x;
    const int N = G3 * HID;
    if (i < N) {
        split2(Wih[i], g_Wih_hi[i], g_Wih_lo[i]);
    } else {
        int j = i - N;
        split2(Whh[j], g_Whh_hi[j], g_Whh_lo[j]);
    }
}

// ---------------- kernel: E = emb @ W_ih^T  (M=32000, N=3072, K=1024) ----------------
// CTA tile 128x128, kc=32, 8 warps as 2(M) x 4(N); warp tile 64x32.
__global__ __launch_bounds__(256) void k_vocab(const float *__restrict__ emb) {
    __shared__ __nv_bfloat16 sA_hi[128 * 40];
    __shared__ __nv_bfloat16 sA_lo[128 * 40];
    __shared__ __nv_bfloat16 sB_hi[128 * 40];
    __shared__ __nv_bfloat16 sB_lo[128 * 40];

    const int tid = threadIdx.x;
    const int lane = tid & 31, warp = tid >> 5;
    const int wm = warp & 1, wn = warp >> 1;
    const int m0 = blockIdx.y * 128, n0 = blockIdx.x * 128;

    float acc[4][4][4] = {};

    const int g  = lane >> 2;
    const int c2 = (lane & 3) * 2;

    for (int kt = 0; kt < 32; ++kt) {
        const int k0 = kt * 32;
        __syncthreads();
        // A tile: 128 x 32 f32 from emb, split to hi/lo bf16
        {
            const int r_ = tid >> 3, c4 = (tid & 7) * 4;
#pragma unroll
            for (int i = 0; i < 4; i++) {
                const int row = r_ + i * 32;
                float4 v = *reinterpret_cast<const float4 *>(
                    &emb[(size_t)(m0 + row) * HID + k0 + c4]);
                __nv_bfloat16 h0, h1, h2, h3, l0, l1, l2, l3;
                split2(v.x, h0, l0); split2(v.y, h1, l1);
                split2(v.z, h2, l2); split2(v.w, h3, l3);
                unsigned *ph = reinterpret_cast<unsigned *>(&sA_hi[row * 40 + c4]);
                ph[0] = pk(h0, h1); ph[1] = pk(h2, h3);
                unsigned *pl = reinterpret_cast<unsigned *>(&sA_lo[row * 40 + c4]);
                pl[0] = pk(l0, l1); pl[1] = pk(l2, l3);
            }
        }
        // B tile: 128 x 32 bf16 (pre-split W_ih)
        {
            const int rb = tid >> 2, q = tid & 3;
#pragma unroll
            for (int i = 0; i < 2; i++) {
                const int row = rb + i * 64;
                *reinterpret_cast<uint4 *>(&sB_hi[row * 40 + q * 8]) =
                    *reinterpret_cast<const uint4 *>(&g_Wih_hi[(size_t)(n0 + row) * HID + k0 + q * 8]);
                *reinterpret_cast<uint4 *>(&sB_lo[row * 40 + q * 8]) =
                    *reinterpret_cast<const uint4 *>(&g_Wih_lo[(size_t)(n0 + row) * HID + k0 + q * 8]);
            }
        }
        __syncthreads();

#pragma unroll
        for (int kk = 0; kk < 32; kk += 16) {
            unsigned ah[4][4], al[4][4];
#pragma unroll
            for (int mf = 0; mf < 4; mf++) {
                const int ra = wm * 64 + mf * 16 + g;
                ah[mf][0] = *reinterpret_cast<unsigned *>(&sA_hi[ra * 40 + kk + c2]);
                ah[mf][1] = *reinterpret_cast<unsigned *>(&sA_hi[(ra + 8) * 40 + kk + c2]);
                ah[mf][2] = *reinterpret_cast<unsigned *>(&sA_hi[ra * 40 + kk + c2 + 8]);
                ah[mf][3] = *reinterpret_cast<unsigned *>(&sA_hi[(ra + 8) * 40 + kk + c2 + 8]);
                al[mf][0] = *reinterpret_cast<unsigned *>(&sA_lo[ra * 40 + kk + c2]);
                al[mf][1] = *reinterpret_cast<unsigned *>(&sA_lo[(ra + 8) * 40 + kk + c2]);
                al[mf][2] = *reinterpret_cast<unsigned *>(&sA_lo[ra * 40 + kk + c2 + 8]);
                al[mf][3] = *reinterpret_cast<unsigned *>(&sA_lo[(ra + 8) * 40 + kk + c2 + 8]);
            }
#pragma unroll
            for (int nf = 0; nf < 4; nf++) {
                const int rb_ = wn * 32 + nf * 8 + g;
                unsigned bh[2], bl[2];
                bh[0] = *reinterpret_cast<unsigned *>(&sB_hi[rb_ * 40 + kk + c2]);
                bh[1] = *reinterpret_cast<unsigned *>(&sB_hi[rb_ * 40 + kk + c2 + 8]);
                bl[0] = *reinterpret_cast<unsigned *>(&sB_lo[rb_ * 40 + kk + c2]);
                bl[1] = *reinterpret_cast<unsigned *>(&sB_lo[rb_ * 40 + kk + c2 + 8]);
#pragma unroll
                for (int mf = 0; mf < 4; mf++) {
                    mma16816(acc[mf][nf], ah[mf], bh);  // hi*hi
                    mma16816(acc[mf][nf], ah[mf], bl);  // hi*lo
                    mma16816(acc[mf][nf], al[mf], bh);  // lo*hi
                }
            }
        }
    }

    // epilogue: write E (no bias here; bias added in the step kernel)
#pragma unroll
    for (int mf = 0; mf < 4; mf++) {
#pragma unroll
        for (int nf = 0; nf < 4; nf++) {
            const int row = m0 + wm * 64 + mf * 16 + g;
            const int col = n0 + wn * 32 + nf * 8 + c2;
            *reinterpret_cast<float2 *>(&g_E[(size_t)row * G3 + col]) =
                make_float2(acc[mf][nf][0], acc[mf][nf][1]);
            *reinterpret_cast<float2 *>(&g_E[(size_t)(row + 8) * G3 + col]) =
                make_float2(acc[mf][nf][2], acc[mf][nf][3]);
        }
    }
}

// ---------------- kernel: one GRU step ----------------
// CTA tile: 32 batch rows x 192 gate-cols (= 64 hidden units x {r,z,n} slabs), K=1024.
// Grid: (16 unit-tiles, 8 batch-tiles) = 128 CTAs. Fused gate nonlinearity + h update.
#define SM_A   (32 * 40)
#define SM_B   (192 * 40)
#define STEP_SMEM_BYTES ((2 * SM_A + 2 * SM_B) * 2)   // 35840 bytes (bf16)

__global__ __launch_bounds__(256) void k_step(const int *__restrict__ inputs,
                                              const float *__restrict__ b_ih,
                                              const float *__restrict__ b_hh,
                                              int t) {
    extern __shared__ char smem[];
    __nv_bfloat16 *sA_hi = reinterpret_cast<__nv_bfloat16 *>(smem);
    __nv_bfloat16 *sA_lo = sA_hi + SM_A;
    __nv_bfloat16 *sB_hi = sA_lo + SM_A;
    __nv_bfloat16 *sB_lo = sB_hi + SM_B;
    float *sHg = reinterpret_cast<float *>(smem);  // 32 x 200 f32 = 25600 B, reused after MMAs

    const float *hin  = (t & 1) ? g_h1 : g_h0;
    float       *hout = (t & 1) ? g_h0 : g_h1;

    const int tid = threadIdx.x;
    const int lane = tid & 31, warp = tid >> 5;
    const int b0 = blockIdx.y * 32;
    const int j0 = blockIdx.x * 64;

    float acc[2][3][4] = {};
    const int g  = lane >> 2;
    const int c2 = (lane & 3) * 2;

    for (int kt = 0; kt < 32; ++kt) {
        const int k0 = kt * 32;
        __syncthreads();
        // A tile: h (32 x 32 f32) -> split bf16
        {
            const int r_ = tid >> 3, c4 = (tid & 7) * 4;
            float4 v = *reinterpret_cast<const float4 *>(&hin[(b0 + r_) * HID + k0 + c4]);
            __nv_bfloat16 h0, h1, h2, h3, l0, l1, l2, l3;
            split2(v.x, h0, l0); split2(v.y, h1, l1);
            split2(v.z, h2, l2); split2(v.w, h3, l3);
            unsigned *ph = reinterpret_cast<unsigned *>(&sA_hi[r_ * 40 + c4]);
            ph[0] = pk(h0, h1); ph[1] = pk(h2, h3);
            unsigned *pl = reinterpret_cast<unsigned *>(&sA_lo[r_ * 40 + c4]);
            pl[0] = pk(l0, l1); pl[1] = pk(l2, l3);
        }
        // B tile: 192 rows of pre-split W_hh; row n -> gate(n/64), unit j0 + n%64
        {
            const int rb = tid >> 2, q = tid & 3;
#pragma unroll
            for (int i = 0; i < 3; i++) {
                const int row  = rb + i * 64;
                const int wrow = (row >> 6) * HID + j0 + (row & 63);
                *reinterpret_cast<uint4 *>(&sB_hi[row * 40 + q * 8]) =
                    *reinterpret_cast<const uint4 *>(&g_Whh_hi[(size_t)wrow * HID + k0 + q * 8]);
                *reinterpret_cast<uint4 *>(&sB_lo[row * 40 + q * 8]) =
                    *reinterpret_cast<const uint4 *>(&g_Whh_lo[(size_t)wrow * HID + k0 + q * 8]);
            }
        }
        __syncthreads();

#pragma unroll
        for (int kk = 0; kk < 32; kk += 16) {
            unsigned ah[2][4], al[2][4];
#pragma unroll
            for (int mf = 0; mf < 2; mf++) {
                const int ra = mf * 16 + g;
                ah[mf][0] = *reinterpret_cast<unsigned *>(&sA_hi[ra * 40 + kk + c2]);
                ah[mf][1] = *reinterpret_cast<unsigned *>(&sA_hi[(ra + 8) * 40 + kk + c2]);
                ah[mf][2] = *reinterpret_cast<unsigned *>(&sA_hi[ra * 40 + kk + c2 + 8]);
                ah[mf][3] = *reinterpret_cast<unsigned *>(&sA_hi[(ra + 8) * 40 + kk + c2 + 8]);
                al[mf][0] = *reinterpret_cast<unsigned *>(&sA_lo[ra * 40 + kk + c2]);
                al[mf][1] = *reinterpret_cast<unsigned *>(&sA_lo[(ra + 8) * 40 + kk + c2]);
                al[mf][2] = *reinterpret_cast<unsigned *>(&sA_lo[ra * 40 + kk + c2 + 8]);
                al[mf][3] = *reinterpret_cast<unsigned *>(&sA_lo[(ra + 8) * 40 + kk + c2 + 8]);
            }
#pragma unroll
            for (int nf = 0; nf < 3; nf++) {
                const int rb_ = warp * 24 + nf * 8 + g;
                unsigned bh[2], bl[2];
                bh[0] = *reinterpret_cast<unsigned *>(&sB_hi[rb_ * 40 + kk + c2]);
                bh[1] = *reinterpret_cast<unsigned *>(&sB_hi[rb_ * 40 + kk + c2 + 8]);
                bl[0] = *reinterpret_cast<unsigned *>(&sB_lo[rb_ * 40 + kk + c2]);
                bl[1] = *reinterpret_cast<unsigned *>(&sB_lo[rb_ * 40 + kk + c2 + 8]);
#pragma unroll
                for (int mf = 0; mf < 2; mf++) {
                    mma16816(acc[mf][nf], ah[mf], bh);
                    mma16816(acc[mf][nf], ah[mf], bl);
                    mma16816(acc[mf][nf], al[mf], bh);
                }
            }
        }
    }
    __syncthreads();  // all MMA smem reads done before overwriting with sHg

    // stage hg tile to shared: sHg[row 0..31][col 0..191], stride 200
#pragma unroll
    for (int mf = 0; mf < 2; mf++) {
#pragma unroll
        for (int nf = 0; nf < 3; nf++) {
            const int r   = mf * 16 + g;
            const int col = warp * 24 + nf * 8 + c2;
            sHg[r * 200 + col]           = acc[mf][nf][0];
            sHg[r * 200 + col + 1]       = acc[mf][nf][1];
            sHg[(r + 8) * 200 + col]     = acc[mf][nf][2];
            sHg[(r + 8) * 200 + col + 1] = acc[mf][nf][3];
        }
    }
    __syncthreads();

    // fused gating + hidden update: thread -> (batch row r, 8 hidden units)
    {
        const int r  = tid >> 3;
        const int u0 = (tid & 7) * 8;
        const int v  = inputs[(b0 + r) * SEQ + t];
        const float *Erow = &g_E[(size_t)v * G3];
#pragma unroll
        for (int uu = 0; uu < 8; ++uu) {
            const int u = u0 + uu;
            const int j = j0 + u;
            const float xr = Erow[j]           + b_ih[j];
            const float xz = Erow[HID + j]     + b_ih[HID + j];
            const float xn = Erow[2 * HID + j] + b_ih[2 * HID + j];
            const float hr = sHg[r * 200 + u]        + b_hh[j];
            const float hz = sHg[r * 200 + 64 + u]   + b_hh[HID + j];
            const float hn = sHg[r * 200 + 128 + u]  + b_hh[2 * HID + j];
            const float rg = 1.0f / (1.0f + __expf(-(xr + hr)));
            const float zg = 1.0f / (1.0f + __expf(-(xz + hz)));
            const float ng = tanhf(xn + rg * hn);
            const float hp = hin[(b0 + r) * HID + j];
            hout[(b0 + r) * HID + j] = (1.0f - zg) * ng + zg * hp;
        }
    }
}

// ---------------- kernel: zero h0 ----------------
__global__ void k_zero() {
    int i = blockIdx.x * blockDim.x + threadIdx.x;
    if (i < BATCH * HID) g_h0[i] = 0.0f;
}

// ---------------- kernel: out = h_final @ W_dense^T + b_dense ----------------
__global__ void k_dense(const float *__restrict__ Wd, const float *__restrict__ bd,
                        float *__restrict__ out) {
    const int gw   = (blockIdx.x * (blockDim.x >> 5)) + (threadIdx.x >> 5);
    const int lane = threadIdx.x & 31;
    if (gw >= BATCH * 2) return;
    const int b = gw >> 1, o = gw & 1;
    const float *h = g_h0;  // after 512 steps, final h lives in g_h0
    float s = 0.0f;
    for (int i = lane; i < HID; i += 32) s += h[b * HID + i] * Wd[o * HID + i];
#pragma unroll
    for (int off = 16; off > 0; off >>= 1) s += __shfl_xor_sync(0xFFFFFFFFu, s, off);
    if (lane == 0) out[b * 2 + o] = s + bd[o];
}

// ---------------- launch ----------------
extern "C" void kernel_launch(void *const *d_in, const int *in_sizes, int n_in,
                              void *d_out, int out_size) {
    const int   *inputs  = (const int *)d_in[0];
    const float *emb     = (const float *)d_in[1];
    const float *W_ih    = (const float *)d_in[2];
    const float *W_hh    = (const float *)d_in[3];
    const float *b_ih    = (const float *)d_in[4];
    const float *b_hh    = (const float *)d_in[5];
    const float *W_dense = (const float *)d_in[6];
    const float *b_dense = (const float *)d_in[7];
    float *out = (float *)d_out;

    // 1) split weights to bf16 hi/lo (2 * 3072*1024 elements, exact grid)
    k_split<<<6144, 1024>>>(W_ih, W_hh);
    // 2) vocab-factorized input GEMM: E[32000,3072] = emb @ W_ih^T
    k_vocab<<<dim3(24, 250), 256>>>(emb);
    // 3) h0 = 0
    k_zero<<<256, 1024>>>();
    // 4) 512 sequential GRU steps (ping-pong g_h0/g_h1)
    for (int t = 0; t < SEQ; ++t)
        k_step<<<dim3(16, 8), 256, STEP_SMEM_BYTES>>>(inputs, b_ih, b_hh, t);
    // 5) final dense head: 512 warps, one per (batch, out) pair
    k_dense<<<64, 256>>>(W_dense, b_dense, out);
}